// round 17
// baseline (speedup 1.0000x reference)
#include <cuda_runtime.h>
#include <cuda_fp16.h>
#include <cstdint>

#define D        512
#define MAXN     50000
#define MAXE     800000
#define SCANB    ((MAXN + 1023) / 1024)   // 49 blocks

// ---------------- device scratch ----------------
__device__ __half g_yh[(size_t)MAXN * D];   // y = x @ W^T in fp16
__device__ __half g_xh[(size_t)MAXN * D];   // x converted to fp16
__device__ __half g_wh[(size_t)D * D];      // W converted to fp16 [n][k]
__device__ float  g_deg[MAXN];              // source-degree
__device__ int    g_cnt[MAXN];              // col histogram
__device__ int    g_off[MAXN + 1];          // CSC partial offsets (scanA output)
__device__ int    g_cur[MAXN];              // fill cursors
__device__ int2   g_spack[MAXE];            // packed (srow, norm-bits) by destination
__device__ int    g_bsum[SCANB];
__device__ int    g_boff[SCANB];            // per-block exclusive offsets
__device__ int    g_done;                   // scan last-block arrival counter

// ---------------- inline dtype sniff ----------------
__device__ __forceinline__ int sniff_is64(const int* ei32) {
    int lane = threadIdx.x & 31;
    int v = ei32[2 * lane + 1];
    unsigned nz = __ballot_sync(0xffffffffu, v != 0);
    return nz == 0u;
}

__device__ __forceinline__ int load_idx(const void* ei, long long pos, int is64) {
    if (is64) return (int)((const long long*)ei)[pos];
    return ((const int*)ei)[pos];
}

__device__ __forceinline__ int final_off(int i) {
    return (i == 0) ? 0 : (g_off[i] + g_boff[(i - 1) >> 10]);
}

// ---------------- prep: zero small arrays + convert x,W -> fp16 -------------
__global__ void __launch_bounds__(256)
prep_kernel(const float* __restrict__ x, const float* __restrict__ W, int n_nodes) {
    size_t t = (size_t)blockIdx.x * blockDim.x + threadIdx.x;
    size_t stride = (size_t)gridDim.x * blockDim.x;

    for (size_t i = t; i < (size_t)n_nodes; i += stride) {
        g_deg[i] = 0.f;
        g_cnt[i] = 0;
        g_cur[i] = 0;
    }
    if (t == 0) g_done = 0;

    size_t wtotal8 = (size_t)D * D / 8;
    for (size_t k = t; k < wtotal8; k += stride) {
        float4 f0 = ((const float4*)W)[2 * k];
        float4 f1 = ((const float4*)W)[2 * k + 1];
        __half2 h0 = __floats2half2_rn(f0.x, f0.y);
        __half2 h1 = __floats2half2_rn(f0.z, f0.w);
        __half2 h2 = __floats2half2_rn(f1.x, f1.y);
        __half2 h3 = __floats2half2_rn(f1.z, f1.w);
        uint4 p;
        p.x = *(uint32_t*)&h0; p.y = *(uint32_t*)&h1;
        p.z = *(uint32_t*)&h2; p.w = *(uint32_t*)&h3;
        ((uint4*)g_wh)[k] = p;
    }

    size_t xtotal8 = (size_t)n_nodes * D / 8;
    for (size_t k = t; k < xtotal8; k += stride) {
        float4 f0 = ((const float4*)x)[2 * k];
        float4 f1 = ((const float4*)x)[2 * k + 1];
        __half2 h0 = __floats2half2_rn(f0.x, f0.y);
        __half2 h1 = __floats2half2_rn(f0.z, f0.w);
        __half2 h2 = __floats2half2_rn(f1.x, f1.y);
        __half2 h3 = __floats2half2_rn(f1.z, f1.w);
        uint4 p;
        p.x = *(uint32_t*)&h0; p.y = *(uint32_t*)&h1;
        p.z = *(uint32_t*)&h2; p.w = *(uint32_t*)&h3;
        ((uint4*)g_xh)[k] = p;
    }
}

// ---------------- fused GEMM(y = x@W^T, fp16 out) + histogram ---------------
// Blocks [0, eblocks): edge histograms (atomic-bound).
// Blocks [eblocks, ...): fp16 tensor GEMM writing y (tensor-bound).
// The two populations overlap in one launch; GEMM depends only on prep.
#define KC       64
#define HPITCH   72                          // 36-word pitch, conflict-free
#define GSMEM    (4 * 128 * HPITCH * 2)      // 73728 B

__device__ __forceinline__ void cp_async16(uint32_t smem, const void* gptr, int valid) {
    asm volatile("cp.async.cg.shared.global [%0], [%1], 16, %2;\n"
                 :: "r"(smem), "l"(gptr), "r"(valid ? 16 : 0));
}
__device__ __forceinline__ void cp_commit() {
    asm volatile("cp.async.commit_group;\n" ::: "memory");
}
__device__ __forceinline__ void cp_wait1() {
    asm volatile("cp.async.wait_group 1;\n" ::: "memory");
}
__device__ __forceinline__ void cp_wait0() {
    asm volatile("cp.async.wait_group 0;\n" ::: "memory");
}

__global__ void __launch_bounds__(256, 2)
gemmhist_kernel(const void* __restrict__ ei, int E, int n_nodes, int eblocks,
                int Nrows) {
    if ((int)blockIdx.x < eblocks) {
        // ---- histogram branch ----
        int is64 = sniff_is64((const int*)ei);
        int e = blockIdx.x * 256 + threadIdx.x;
        if (e >= E) return;
        int r = load_idx(ei, e, is64);
        int c = load_idx(ei, (long long)E + e, is64);
        atomicAdd(&g_deg[r], 1.0f);
        atomicAdd(&g_cnt[c], 1);
        return;
    }

    // ---- GEMM branch: y[m][n] = sum_k x[m][k] * W[n][k], fp16 out ----
    const __half* __restrict__ A = g_xh;
    const __half* __restrict__ B = g_wh;

    extern __shared__ __half sdyn[];
    __half* As0 = sdyn;
    __half* As1 = As0 + 128 * HPITCH;
    __half* Bs0 = As1 + 128 * HPITCH;
    __half* Bs1 = Bs0 + 128 * HPITCH;

    const int bid2 = blockIdx.x - eblocks;
    const int m0   = (bid2 >> 2) * 128;
    const int n0   = (bid2 & 3) * 128;

    const int tid  = threadIdx.x;
    const int warp = tid >> 5;
    const int lane = tid & 31;
    const int g    = lane >> 2;
    const int tg   = lane & 3;
    const int wm   = warp >> 2;
    const int wn   = warp & 3;

    float acc[4][4][4];
#pragma unroll
    for (int i = 0; i < 4; i++)
#pragma unroll
        for (int j = 0; j < 4; j++)
#pragma unroll
            for (int r = 0; r < 4; r++) acc[i][j][r] = 0.f;

    uint32_t sA0 = (uint32_t)__cvta_generic_to_shared(As0);
    uint32_t sA1 = (uint32_t)__cvta_generic_to_shared(As1);
    uint32_t sB0 = (uint32_t)__cvta_generic_to_shared(Bs0);
    uint32_t sB1 = (uint32_t)__cvta_generic_to_shared(Bs1);

#define ISSUE_TILE(buf, k0)                                                          \
    do {                                                                             \
        uint32_t sa = (buf) ? sA1 : sA0;                                             \
        uint32_t sb = (buf) ? sB1 : sB0;                                             \
        _Pragma("unroll")                                                            \
        for (int i = 0; i < 4; i++) {                                                \
            int idx = i * 256 + tid;                                                 \
            int row = idx >> 3, c8 = idx & 7;                                        \
            int grow = m0 + row;                                                     \
            const __half* gp = A + (size_t)grow * D + (k0) + c8 * 8;                 \
            cp_async16(sa + (row * HPITCH + c8 * 8) * 2, gp, grow < Nrows);          \
        }                                                                            \
        _Pragma("unroll")                                                            \
        for (int i = 0; i < 4; i++) {                                                \
            int idx = i * 256 + tid;                                                 \
            int row = idx >> 3, c8 = idx & 7;                                        \
            const __half* gp = B + (size_t)(n0 + row) * D + (k0) + c8 * 8;           \
            cp_async16(sb + (row * HPITCH + c8 * 8) * 2, gp, 1);                     \
        }                                                                            \
    } while (0)

    ISSUE_TILE(0, 0);
    cp_commit();

    const int NCHUNK = D / KC;   // 8
    for (int kc = 0; kc < NCHUNK; kc++) {
        int buf = kc & 1;
        if (kc + 1 < NCHUNK) {
            ISSUE_TILE((kc + 1) & 1, (kc + 1) * KC);
            cp_commit();
            cp_wait1();
        } else {
            cp_wait0();
        }
        __syncthreads();

        const __half* as = buf ? As1 : As0;
        const __half* bs = buf ? Bs1 : Bs0;

#pragma unroll
        for (int ks = 0; ks < 4; ks++) {
            int kk = ks * 16;
            uint32_t af[4][4], bf[4][2];
#pragma unroll
            for (int mi = 0; mi < 4; mi++) {
                int rb = wm * 64 + mi * 16;
                af[mi][0] = *(const uint32_t*)(as + (rb + g)     * HPITCH + kk + 2 * tg);
                af[mi][1] = *(const uint32_t*)(as + (rb + g + 8) * HPITCH + kk + 2 * tg);
                af[mi][2] = *(const uint32_t*)(as + (rb + g)     * HPITCH + kk + 2 * tg + 8);
                af[mi][3] = *(const uint32_t*)(as + (rb + g + 8) * HPITCH + kk + 2 * tg + 8);
            }
#pragma unroll
            for (int nj = 0; nj < 4; nj++) {
                int nb = wn * 32 + nj * 8;
                bf[nj][0] = *(const uint32_t*)(bs + (nb + g) * HPITCH + kk + 2 * tg);
                bf[nj][1] = *(const uint32_t*)(bs + (nb + g) * HPITCH + kk + 2 * tg + 8);
            }
#pragma unroll
            for (int mi = 0; mi < 4; mi++)
#pragma unroll
                for (int nj = 0; nj < 4; nj++) {
                    asm volatile(
                        "mma.sync.aligned.m16n8k16.row.col.f32.f16.f16.f32 "
                        "{%0,%1,%2,%3}, {%4,%5,%6,%7}, {%8,%9}, {%0,%1,%2,%3};"
                        : "+f"(acc[mi][nj][0]), "+f"(acc[mi][nj][1]),
                          "+f"(acc[mi][nj][2]), "+f"(acc[mi][nj][3])
                        : "r"(af[mi][0]), "r"(af[mi][1]), "r"(af[mi][2]), "r"(af[mi][3]),
                          "r"(bf[nj][0]), "r"(bf[nj][1]));
                }
        }
        __syncthreads();
    }

    // epilogue: pack to fp16, store y
#pragma unroll
    for (int mi = 0; mi < 4; mi++) {
        int r0 = m0 + wm * 64 + mi * 16 + g;
        int r1 = r0 + 8;
#pragma unroll
        for (int nj = 0; nj < 4; nj++) {
            int cn = n0 + wn * 32 + nj * 8 + 2 * tg;
            if (r0 < Nrows) {
                __half2 h = __floats2half2_rn(acc[mi][nj][0], acc[mi][nj][1]);
                *(uint32_t*)(g_yh + (size_t)r0 * D + cn) = *(uint32_t*)&h;
            }
            if (r1 < Nrows) {
                __half2 h = __floats2half2_rn(acc[mi][nj][2], acc[mi][nj][3]);
                *(uint32_t*)(g_yh + (size_t)r1 * D + cn) = *(uint32_t*)&h;
            }
        }
    }
#undef ISSUE_TILE
}

// ---------------- scan: phase A per-block + fused phase B in last block -----
__device__ __forceinline__ int block_scan_1024(int v, int* warpsum) {
    const int lane = threadIdx.x & 31;
    const int wid  = threadIdx.x >> 5;
#pragma unroll
    for (int d = 1; d < 32; d <<= 1) {
        int tt = __shfl_up_sync(0xffffffffu, v, d);
        if (lane >= d) v += tt;
    }
    if (lane == 31) warpsum[wid] = v;
    __syncthreads();
    if (wid == 0) {
        int s = warpsum[lane];
#pragma unroll
        for (int d = 1; d < 32; d <<= 1) {
            int tt = __shfl_up_sync(0xffffffffu, s, d);
            if (lane >= d) s += tt;
        }
        warpsum[lane] = s;
    }
    __syncthreads();
    return v + ((wid > 0) ? warpsum[wid - 1] : 0);
}

__global__ void __launch_bounds__(1024)
scanAB_kernel(int n, int nb) {
    __shared__ int warpsum[32];
    __shared__ int is_last;
    int i = blockIdx.x * 1024 + threadIdx.x;
    int v = (i < n) ? g_cnt[i] : 0;
    int incl = block_scan_1024(v, warpsum);
    if (i < n) g_off[i + 1] = incl;
    if (i == 0) g_off[0] = 0;

    if (threadIdx.x == 1023) {
        g_bsum[blockIdx.x] = incl;
        __threadfence();
        int prev = atomicAdd(&g_done, 1);
        is_last = (prev == nb - 1);
    }
    __syncthreads();

    if (is_last) {
        __threadfence();
        int vv = (threadIdx.x < nb) ? g_bsum[threadIdx.x] : 0;
        int inc2 = block_scan_1024(vv, warpsum);
        if (threadIdx.x < nb) g_boff[threadIdx.x] = inc2 - vv;
        if (threadIdx.x == 0) g_done = 0;
    }
}

// ---------------- fused fill (packed int2 store) ----------------
__global__ void fill_kernel(const void* __restrict__ ei,
                            const float* __restrict__ edge_attr,
                            const float* __restrict__ conf_w,
                            const float* __restrict__ conf_b,
                            int E) {
    int is64 = sniff_is64((const int*)ei);
    int e = blockIdx.x * blockDim.x + threadIdx.x;
    if (e >= E) return;
    int r = load_idx(ei, e, is64);
    int c = load_idx(ei, (long long)E + e, is64);

    float z = edge_attr[3 * e + 0] * conf_w[0]
            + edge_attr[3 * e + 1] * conf_w[1]
            + edge_attr[3 * e + 2] * conf_w[2]
            + conf_b[0];
    float ew = 1.0f / (1.0f + expf(-z));

    float dr = g_deg[r];
    float dc = g_deg[c];
    float ir = (dr > 0.f) ? rsqrtf(dr) : 0.f;
    float ic = (dc > 0.f) ? rsqrtf(dc) : 0.f;
    float nrm = ir * ic * ew;
    if (isnan(nrm)) nrm = 0.f;

    int pos = final_off(c) + atomicAdd(&g_cur[c], 1);
    g_spack[pos] = make_int2(r, __float_as_int(nrm));
}

// ---------------- aggregate y rows -> out (fp32, + bias) --------------------
// One warp per destination node; gathers y (fp16), fp32 accumulate,
// adds bias, writes fp32 out with streaming stores.
__device__ __forceinline__ void acc_u4(float2* a, uint4 u, float n) {
    const __half2* h = (const __half2*)&u;
#pragma unroll
    for (int j = 0; j < 4; j++) {
        float2 f = __half22float2(h[j]);
        a[j].x = fmaf(f.x, n, a[j].x);
        a[j].y = fmaf(f.y, n, a[j].y);
    }
}

__global__ void __launch_bounds__(256)
aggregate_out_kernel(const float* __restrict__ bias,
                     float* __restrict__ out,
                     int n_nodes) {
    int node = (blockIdx.x * blockDim.x + threadIdx.x) >> 5;
    int lane = threadIdx.x & 31;
    if (node >= n_nodes) return;

    int beg = final_off(node);
    int end = final_off(node + 1);

    float2 a[8];
#pragma unroll
    for (int j = 0; j < 8; j++) a[j] = make_float2(0.f, 0.f);

    int i = beg;
    for (; i + 1 < end; i += 2) {
        int2 pA = g_spack[i];
        int2 pB = g_spack[i + 1];
        float nA = __int_as_float(pA.y);
        float nB = __int_as_float(pB.y);
        const uint4* yA = (const uint4*)(g_yh + (size_t)pA.x * D);
        const uint4* yB = (const uint4*)(g_yh + (size_t)pB.x * D);
        uint4 uA0 = yA[lane];
        uint4 uA1 = yA[lane + 32];
        uint4 uB0 = yB[lane];
        uint4 uB1 = yB[lane + 32];
        acc_u4(a,     uA0, nA);
        acc_u4(a + 4, uA1, nA);
        acc_u4(a,     uB0, nB);
        acc_u4(a + 4, uB1, nB);
    }
    if (i < end) {
        int2 p = g_spack[i];
        float nm = __int_as_float(p.y);
        const uint4* yr = (const uint4*)(g_yh + (size_t)p.x * D);
        uint4 u0 = yr[lane];
        uint4 u1 = yr[lane + 32];
        acc_u4(a,     u0, nm);
        acc_u4(a + 4, u1, nm);
    }

    // add bias and write fp32 out (streaming)
    const float4* bias4 = (const float4*)bias;
    float4* orow = (float4*)(out + (size_t)node * D);
    float4 b0 = bias4[2 * lane];
    float4 b1 = bias4[2 * lane + 1];
    float4 b2 = bias4[2 * lane + 64];
    float4 b3 = bias4[2 * lane + 65];
    float4 v0 = make_float4(a[0].x + b0.x, a[0].y + b0.y, a[1].x + b0.z, a[1].y + b0.w);
    float4 v1 = make_float4(a[2].x + b1.x, a[2].y + b1.y, a[3].x + b1.z, a[3].y + b1.w);
    float4 v2 = make_float4(a[4].x + b2.x, a[4].y + b2.y, a[5].x + b2.z, a[5].y + b2.w);
    float4 v3 = make_float4(a[6].x + b3.x, a[6].y + b3.y, a[7].x + b3.z, a[7].y + b3.w);
    __stcs(orow + 2 * lane, v0);
    __stcs(orow + 2 * lane + 1, v1);
    __stcs(orow + 2 * lane + 64, v2);
    __stcs(orow + 2 * lane + 65, v3);
}

// ---------------- launch ----------------
extern "C" void kernel_launch(void* const* d_in, const int* in_sizes, int n_in,
                              void* d_out, int out_size) {
    const float* x         = (const float*)d_in[0];
    const void*  ei        = d_in[1];
    const float* edge_attr = (const float*)d_in[2];
    const float* lin_w     = (const float*)d_in[3];
    const float* lin_b     = (const float*)d_in[4];
    const float* conf_w    = (const float*)d_in[5];
    const float* conf_b    = (const float*)d_in[6];
    float* out             = (float*)d_out;

    const int n_nodes = in_sizes[0] / D;
    const int E       = in_sizes[2] / 3;
    const int nb      = (n_nodes + 1023) / 1024;
    const int eblocks = (E + 255) / 256;
    const int mblocks = (n_nodes + 127) / 128;

    static int smem_set = 0;
    if (!smem_set) {
        cudaFuncSetAttribute(gemmhist_kernel,
                             cudaFuncAttributeMaxDynamicSharedMemorySize, GSMEM);
        smem_set = 1;
    }

    prep_kernel<<<1024, 256>>>(x, lin_w, n_nodes);

    gemmhist_kernel<<<eblocks + mblocks * 4, 256, GSMEM>>>(ei, E, n_nodes,
                                                           eblocks, n_nodes);

    scanAB_kernel<<<nb, 1024>>>(n_nodes, nb);

    fill_kernel<<<eblocks, 256>>>(ei, edge_attr, conf_w, conf_b, E);

    {
        int warps_per_block = 256 / 32;
        int blocks = (n_nodes + warps_per_block - 1) / warps_per_block;
        aggregate_out_kernel<<<blocks, 256>>>(lin_b, out, n_nodes);
    }
}